// round 16
// baseline (speedup 1.0000x reference)
#include <cuda_runtime.h>
#include <cuda_bf16.h>
#include <math.h>
#include <math_constants.h>
#include <cstdint>

// Problem constants
#define NB 2
#define NS 2048
#define ND 2048
#define NH 16
#define DH 128
#define NM 4096   // NB*NS

#define L2_10K_OVER_64 0.2076205059304602f   // log2(10000)/64
#define QSCALE 0.08838834764831845f          // 1/sqrt(128)

// Scratch: sanctioned __device__ globals (no runtime allocation).
__device__ __nv_bfloat16 g_xh [NM*ND];         // activation hi (x, then attn-out)
__device__ __nv_bfloat16 g_xl [NM*ND];         // activation lo
__device__ __nv_bfloat16 g_wh [4*ND*ND];       // transposed weights hi [w][n][k]
__device__ __nv_bfloat16 g_wl [4*ND*ND];       // transposed weights lo
__device__ __nv_bfloat16 g_qh [NB*NH*NS*DH];   // Q hi  (B,H,S,D), roped+scaled
__device__ __nv_bfloat16 g_ql [NB*NH*NS*DH];
__device__ __nv_bfloat16 g_kh [NB*NH*NS*DH];   // K hi  (B,H,S,D), roped
__device__ __nv_bfloat16 g_kl [NB*NH*NS*DH];
__device__ __nv_bfloat16 g_vth[NB*NH*DH*NS];   // V^T hi (B,H,D,S)
__device__ __nv_bfloat16 g_vtl[NB*NH*DH*NS];
__device__ float2 g_rope[NS*64];               // (cos,sin) per (s, freq-index)

struct OutPtrs {
    __nv_bfloat16 *qh, *ql, *kh, *kl, *vth, *vtl;
};

// ============================ PTX helpers ==================================
__device__ __forceinline__ uint32_t smem_u32(const void* p) {
    uint32_t a;
    asm("{ .reg .u64 t; cvta.to.shared.u64 t, %1; cvt.u32.u64 %0, t; }"
        : "=r"(a) : "l"(p));
    return a;
}

__device__ __forceinline__ void ldsm4(uint32_t* r, uint32_t addr) {
    asm volatile("ldmatrix.sync.aligned.m8n8.x4.shared.b16 {%0,%1,%2,%3}, [%4];"
        : "=r"(r[0]), "=r"(r[1]), "=r"(r[2]), "=r"(r[3]) : "r"(addr));
}

__device__ __forceinline__ void mma_bf16(float* c, const uint32_t* a,
                                         uint32_t b0, uint32_t b1) {
    asm volatile(
        "mma.sync.aligned.m16n8k16.row.col.f32.bf16.bf16.f32 "
        "{%0,%1,%2,%3}, {%4,%5,%6,%7}, {%8,%9}, {%0,%1,%2,%3};"
        : "+f"(c[0]), "+f"(c[1]), "+f"(c[2]), "+f"(c[3])
        : "r"(a[0]), "r"(a[1]), "r"(a[2]), "r"(a[3]), "r"(b0), "r"(b1));
}

__device__ __forceinline__ void cpa16(uint32_t saddr, const void* gaddr) {
    asm volatile("cp.async.cg.shared.global [%0], [%1], 16;"
                 :: "r"(saddr), "l"(gaddr));
}
#define CPA_COMMIT() asm volatile("cp.async.commit_group;")
#define CPA_WAIT1()  asm volatile("cp.async.wait_group 1;")
#define CPA_WAIT0()  asm volatile("cp.async.wait_group 0;")

// pack (a,b) into bf16x2 hi word + bf16x2 lo-residual word
__device__ __forceinline__ void hilo2(float a, float b, uint32_t& hi, uint32_t& lo) {
    __nv_bfloat16 ha = __float2bfloat16_rn(a);
    __nv_bfloat16 hb = __float2bfloat16_rn(b);
    __nv_bfloat162 hp(ha, hb);
    __nv_bfloat162 lp = __floats2bfloat162_rn(a - __bfloat162float(ha),
                                              b - __bfloat162float(hb));
    hi = *reinterpret_cast<uint32_t*>(&hp);
    lo = *reinterpret_cast<uint32_t*>(&lp);
}

// =========================== prep kernels ==================================
__global__ void __launch_bounds__(256) split_act(const float* __restrict__ in,
                                                 __nv_bfloat16* __restrict__ hi,
                                                 __nv_bfloat16* __restrict__ lo) {
    int i = (blockIdx.x * 256 + threadIdx.x) * 4;
    float4 v = *(const float4*)(in + i);
    uint32_t h0, l0, h1, l1;
    hilo2(v.x, v.y, h0, l0);
    hilo2(v.z, v.w, h1, l1);
    *(uint2*)(hi + i) = make_uint2(h0, h1);
    *(uint2*)(lo + i) = make_uint2(l0, l1);
}

// RoPE table: exactly the same FP formula the epilogue used inline.
__global__ void __launch_bounds__(256) rope_table(float2* __restrict__ tab) {
    int idx = blockIdx.x * 256 + threadIdx.x;     // 0 .. NS*64-1
    int ss  = idx >> 6;
    int i   = idx & 63;
    float inv = exp2f(-(float)i * L2_10K_OVER_64);
    float s, c;
    sincosf((float)ss * inv, &s, &c);
    tab[idx] = make_float2(c, s);
}

// All four W[k][n] fp32 -> Wt hi/lo bf16 [w][n][k] in ONE launch (grid.z = w)
__global__ void __launch_bounds__(256) split_wT4(
    const float* __restrict__ W0, const float* __restrict__ W1,
    const float* __restrict__ W2, const float* __restrict__ W3,
    __nv_bfloat16* __restrict__ th, __nv_bfloat16* __restrict__ tl) {
    __shared__ float t[32][33];
    const int w  = blockIdx.z;
    const float* W = (w == 0) ? W0 : (w == 1) ? W1 : (w == 2) ? W2 : W3;
    const size_t wo = (size_t)w * ND * ND;
    const int bx = blockIdx.x * 32;   // n tile
    const int by = blockIdx.y * 32;   // k tile
    const int tx = threadIdx.x, ty = threadIdx.y;
#pragma unroll
    for (int j = ty; j < 32; j += 8)
        t[j][tx] = W[(size_t)(by + j) * ND + bx + tx];
    __syncthreads();
#pragma unroll
    for (int j = ty; j < 32; j += 8) {
        float v = t[tx][j];           // = W[by+tx][bx+j]
        __nv_bfloat16 h = __float2bfloat16_rn(v);
        __nv_bfloat16 l = __float2bfloat16_rn(v - __bfloat162float(h));
        th[wo + (size_t)(bx + j) * ND + by + tx] = h;
        tl[wo + (size_t)(bx + j) * ND + by + tx] = l;
    }
}

// ===================== HMMA bf16x3 GEMM mainloop ===========================
// 512 threads / CTA, 16 warps (wm 4 x wn 4), warp tile 32x32, CTA 128x128,
// K_blk = 32, cp.async double buffer, occ 2 (8 warps/SMSP).
#define APITCH 80
#define TILE_BYTES (128 * APITCH)
#define STAGE_BYTES (4 * TILE_BYTES)
#define GSMEM (2 * STAGE_BYTES)            // 81920

// Arow/Brow pre-offset to the CTA tile's first row; row stride ND.
__device__ __forceinline__ void mma_mainloop(
    float acc[2][4][4],
    const __nv_bfloat16* __restrict__ ArowH, const __nv_bfloat16* __restrict__ ArowL,
    const __nv_bfloat16* __restrict__ BrowH, const __nv_bfloat16* __restrict__ BrowL,
    uint32_t sbase, int tid, int wm, int wn, int lane)
{
    auto load_stage = [&](int buf, int k0) {
#pragma unroll
        for (int t = 0; t < 4; ++t) {
            int id   = tid + t * 512;
            int tile = id >> 9;
            int rem  = id & 511;
            int r    = rem >> 2;
            int c    = rem & 3;
            uint32_t so = sbase + buf * STAGE_BYTES + tile * TILE_BYTES
                        + r * APITCH + c * 16;
            const __nv_bfloat16* g;
            if      (tile == 0) g = ArowH + (size_t)r * ND + k0 + c * 8;
            else if (tile == 1) g = ArowL + (size_t)r * ND + k0 + c * 8;
            else if (tile == 2) g = BrowH + (size_t)r * ND + k0 + c * 8;
            else                g = BrowL + (size_t)r * ND + k0 + c * 8;
            cpa16(so, g);
        }
        CPA_COMMIT();
    };

    load_stage(0, 0);

    for (int it = 0; it < 64; ++it) {
        const int buf = it & 1;
        if (it + 1 < 64) { load_stage(buf ^ 1, (it + 1) * 32); CPA_WAIT1(); }
        else             { CPA_WAIT0(); }
        __syncthreads();

        const uint32_t sA  = sbase + buf * STAGE_BYTES;
        const uint32_t sAl = sA + TILE_BYTES;
        const uint32_t sB  = sA + 2 * TILE_BYTES;
        const uint32_t sBl = sA + 3 * TILE_BYTES;

#pragma unroll
        for (int ks = 0; ks < 2; ++ks) {
            const int akb = ks * 32 + (lane >> 4) * 16;
            uint32_t ah[2][4], al[2][4];
#pragma unroll
            for (int mf = 0; mf < 2; ++mf) {
                uint32_t ro = (wm * 32 + mf * 16 + (lane & 15)) * APITCH + akb;
                ldsm4(ah[mf], sA  + ro);
                ldsm4(al[mf], sAl + ro);
            }
            const int brow = wn * 32 + (lane & 7) + ((lane >> 4) << 3);
            const int bkb  = ks * 32 + ((lane >> 3) & 1) * 16;
#pragma unroll
            for (int nf2 = 0; nf2 < 2; ++nf2) {
                uint32_t bo = (brow + nf2 * 16) * APITCH + bkb;
                uint32_t bh[4], bl[4];
                ldsm4(bh, sB  + bo);
                ldsm4(bl, sBl + bo);
                // Per-acc order unchanged (hh -> hl -> lh) => bitwise-identical.
#pragma unroll
                for (int half = 0; half < 2; ++half)
#pragma unroll
                    for (int mf = 0; mf < 2; ++mf)
                        mma_bf16(acc[mf][nf2 * 2 + half], ah[mf],
                                 bh[half * 2], bh[half * 2 + 1]);
#pragma unroll
                for (int half = 0; half < 2; ++half)
#pragma unroll
                    for (int mf = 0; mf < 2; ++mf)
                        mma_bf16(acc[mf][nf2 * 2 + half], ah[mf],
                                 bl[half * 2], bl[half * 2 + 1]);
#pragma unroll
                for (int half = 0; half < 2; ++half)
#pragma unroll
                    for (int mf = 0; mf < 2; ++mf)
                        mma_bf16(acc[mf][nf2 * 2 + half], al[mf],
                                 bh[half * 2], bh[half * 2 + 1]);
            }
        }
        __syncthreads();
    }
}

// ---- merged Q/K/V projections: grid.x = 48 (mode = blockIdx.x >> 4) ----
__global__ void __launch_bounds__(512, 2) gemm_qkv(
    const __nv_bfloat16* __restrict__ Ah, const __nv_bfloat16* __restrict__ Al,
    const __nv_bfloat16* __restrict__ Wh, const __nv_bfloat16* __restrict__ Wl,
    const float2* __restrict__ rope, OutPtrs op)
{
    extern __shared__ char smc[];
    const uint32_t sbase = smem_u32(smc);
    const int tid  = threadIdx.x;
    const int wid  = tid >> 5;
    const int lane = tid & 31;
    const int wm   = wid & 3;
    const int wn   = wid >> 2;                     // 0..3
    const int mode = blockIdx.x >> 4;              // 0=Q 1=K 2=V
    const int col0 = (blockIdx.x & 15) * 128;
    const int row0 = blockIdx.y * 128;
    const size_t wo = (size_t)mode * ND * ND;

    float acc[2][4][4];
#pragma unroll
    for (int mf = 0; mf < 2; ++mf)
#pragma unroll
        for (int nf = 0; nf < 4; ++nf)
#pragma unroll
            for (int e = 0; e < 4; ++e) acc[mf][nf][e] = 0.f;

    mma_mainloop(acc, Ah + (size_t)row0 * ND, Al + (size_t)row0 * ND,
                 Wh + wo + (size_t)col0 * ND, Wl + wo + (size_t)col0 * ND,
                 sbase, tid, wm, wn, lane);

    __nv_bfloat16* Ch = (mode == 0) ? op.qh : (mode == 1) ? op.kh : op.vth;
    __nv_bfloat16* Cl = (mode == 0) ? op.ql : (mode == 1) ? op.kl : op.vtl;

#pragma unroll
    for (int mf = 0; mf < 2; ++mf) {
        const int mrow = row0 + wm * 32 + mf * 16 + (lane >> 2);
#pragma unroll
        for (int rr = 0; rr < 2; ++rr) {
            const int m  = mrow + rr * 8;
            const int bb = m >> 11, ss = m & 2047;
#pragma unroll
            for (int nf = 0; nf < 4; ++nf) {
                const int cloc = wn * 32 + nf * 8 + ((lane & 3) << 1);
                const int col  = col0 + cloc;
                const int h    = col >> 7;
                const int d    = cloc & 127;
                float v0 = acc[mf][nf][rr * 2 + 0];
                float v1 = acc[mf][nf][rr * 2 + 1];
                if (mode == 2) {
                    size_t vb = ((size_t)(bb * NH + h) * DH + d) * NS + ss;
                    __nv_bfloat16 h0 = __float2bfloat16_rn(v0);
                    __nv_bfloat16 h1 = __float2bfloat16_rn(v1);
                    Ch[vb]      = h0;
                    Ch[vb + NS] = h1;
                    Cl[vb]      = __float2bfloat16_rn(v0 - __bfloat162float(h0));
                    Cl[vb + NS] = __float2bfloat16_rn(v1 - __bfloat162float(h1));
                } else {
                    size_t ob = (((size_t)(bb * NH + h) * NS + ss) << 7) + d;
                    // d even, so (d&63) even: one aligned float4 covers both
                    // (cos_e, sin_e, cos_o, sin_o) — same values sincosf gave.
                    float4 cs = *(const float4*)(rope + (size_t)ss * 64 + (d & 63));
                    float o0 = v0 * cs.x - v1 * cs.y;
                    float o1 = v1 * cs.z + v0 * cs.w;
                    if (mode == 0) { o0 *= QSCALE; o1 *= QSCALE; }
                    uint32_t hp, lp;
                    hilo2(o0, o1, hp, lp);
                    *reinterpret_cast<uint32_t*>(Ch + ob) = hp;
                    *reinterpret_cast<uint32_t*>(Cl + ob) = lp;
                }
            }
        }
    }
}

// ---- final projection: fp32 row-major out ----
__global__ void __launch_bounds__(512, 2) gemm_out(
    const __nv_bfloat16* __restrict__ Ah, const __nv_bfloat16* __restrict__ Al,
    const __nv_bfloat16* __restrict__ Wh, const __nv_bfloat16* __restrict__ Wl,
    float* __restrict__ C)
{
    extern __shared__ char smc[];
    const uint32_t sbase = smem_u32(smc);
    const int tid  = threadIdx.x;
    const int wid  = tid >> 5;
    const int lane = tid & 31;
    const int wm   = wid & 3;
    const int wn   = wid >> 2;
    const int col0 = blockIdx.x * 128;
    const int row0 = blockIdx.y * 128;

    float acc[2][4][4];
#pragma unroll
    for (int mf = 0; mf < 2; ++mf)
#pragma unroll
        for (int nf = 0; nf < 4; ++nf)
#pragma unroll
            for (int e = 0; e < 4; ++e) acc[mf][nf][e] = 0.f;

    mma_mainloop(acc, Ah + (size_t)row0 * ND, Al + (size_t)row0 * ND,
                 Wh + (size_t)col0 * ND, Wl + (size_t)col0 * ND,
                 sbase, tid, wm, wn, lane);

#pragma unroll
    for (int mf = 0; mf < 2; ++mf) {
        const int mrow = row0 + wm * 32 + mf * 16 + (lane >> 2);
#pragma unroll
        for (int rr = 0; rr < 2; ++rr) {
            const int m = mrow + rr * 8;
#pragma unroll
            for (int nf = 0; nf < 4; ++nf) {
                const int col = col0 + wn * 32 + nf * 8 + ((lane & 3) << 1);
                *(float2*)(C + (size_t)m * ND + col) =
                    make_float2(acc[mf][nf][rr * 2 + 0], acc[mf][nf][rr * 2 + 1]);
            }
        }
    }
}

// ======================= flash attention (mma.sync) ========================
// Unchanged (known-good). Paired q-tiles per CTA, grid 256 CTAs.
#define NQT (NS / 128)                // 16
#define QPB 272
#define VPB 144
#define OQH 0
#define OQL (OQH + 128*QPB)
#define OKH (OQL + 128*QPB)
#define OKL (OKH + 2*64*QPB)
#define OVH (OKL + 2*64*QPB)
#define OVL (OVH + 2*128*VPB)
#define FSMEM (OVL + 2*128*VPB)       // 212992

__global__ void __launch_bounds__(256, 1) flash_mma(
    const __nv_bfloat16* __restrict__ Qh, const __nv_bfloat16* __restrict__ Ql,
    const __nv_bfloat16* __restrict__ Kh, const __nv_bfloat16* __restrict__ Kl,
    const __nv_bfloat16* __restrict__ Vth, const __nv_bfloat16* __restrict__ Vtl,
    __nv_bfloat16* __restrict__ Oh, __nv_bfloat16* __restrict__ Ol)
{
    extern __shared__ char smc[];
    const uint32_t sb = smem_u32(smc);
    const int tid = threadIdx.x, wid = tid >> 5, lane = tid & 31;
    const int h  = blockIdx.y, b = blockIdx.z;
    const size_t ho = (size_t)(b * NH + h) * NS * DH;

    const uint32_t a_off  = (uint32_t)((wid * 16 + (lane & 15)) * QPB + (lane >> 4) * 16);
    const uint32_t b_row  = (uint32_t)((lane & 7) + ((lane >> 4) << 3));
    const uint32_t b_koff = (uint32_t)(((lane >> 3) & 1) * 16);

    auto loadKV = [&](int buf, int n0) {
#pragma unroll
        for (int t = 0; t < 8; ++t) {
            int id  = tid + t * 256;
            int arr = id >> 10;
            int rem = id & 1023;
            int r = rem >> 4, c = rem & 15;
            uint32_t so = sb + (arr ? OKL : OKH) + buf * (64 * QPB) + r * QPB + c * 16;
            const __nv_bfloat16* g = (arr ? Kl : Kh) + ho + (size_t)(n0 + r) * DH + c * 8;
            cpa16(so, g);
        }
#pragma unroll
        for (int t = 0; t < 8; ++t) {
            int id  = tid + t * 256;
            int arr = id >> 10;
            int rem = id & 1023;
            int r = rem >> 3, c = rem & 7;
            uint32_t so = sb + (arr ? OVL : OVH) + buf * (128 * VPB) + r * VPB + c * 16;
            const __nv_bfloat16* g = (arr ? Vtl : Vth) + ho + (size_t)r * NS + n0 + c * 8;
            cpa16(so, g);
        }
    };

#pragma unroll 1
    for (int rep = 0; rep < 2; ++rep) {
        const int qt = rep == 0 ? (NQT - 1 - (int)blockIdx.x) : (int)blockIdx.x;
        const int q0 = qt * 128;

#pragma unroll
        for (int t = 0; t < 16; ++t) {
            int id  = tid + t * 256;
            int arr = id >> 11;
            int rem = id & 2047;
            int r = rem >> 4, c = rem & 15;
            uint32_t so = sb + (arr ? OQL : OQH) + r * QPB + c * 16;
            const __nv_bfloat16* g = (arr ? Ql : Qh) + ho + (size_t)(q0 + r) * DH + c * 8;
            cpa16(so, g);
        }
        loadKV(0, 0);
        CPA_COMMIT();

        const int rmin = q0 + wid * 16;
        float o[16][4];
#pragma unroll
        for (int nf = 0; nf < 16; ++nf)
#pragma unroll
            for (int e = 0; e < 4; ++e) o[nf][e] = 0.f;
        float m0 = -CUDART_INF_F, m1 = -CUDART_INF_F, l0 = 0.f, l1 = 0.f;

        const int niter = q0 / 64 + 2;
        for (int it = 0; it < niter; ++it) {
            const int n0 = it * 64, buf = it & 1;
            if (it + 1 < niter) { loadKV(buf ^ 1, (it + 1) * 64); CPA_COMMIT(); CPA_WAIT1(); }
            else                { CPA_WAIT0(); }
            __syncthreads();

            if (n0 <= rmin + 15) {
                float sc[8][4];
#pragma unroll
                for (int nf = 0; nf < 8; ++nf)
#pragma unroll
                    for (int e = 0; e < 4; ++e) sc[nf][e] = 0.f;

                const uint32_t kh_b = sb + OKH + buf * (64 * QPB) + b_row * QPB + b_koff;
                const uint32_t kl_b = sb + OKL + buf * (64 * QPB) + b_row * QPB + b_koff;
#pragma unroll 4
                for (int t = 0; t < 8; ++t) {
                    uint32_t ah[4], av[4];
                    ldsm4(ah, sb + OQH + a_off + t * 32);
                    ldsm4(av, sb + OQL + a_off + t * 32);
#pragma unroll
                    for (int nf2 = 0; nf2 < 4; ++nf2) {
                        uint32_t bh[4], bl[4];
                        ldsm4(bh, kh_b + nf2 * (16 * QPB) + t * 32);
                        ldsm4(bl, kl_b + nf2 * (16 * QPB) + t * 32);
                        mma_bf16(sc[2*nf2],   ah, bh[0], bh[1]);
                        mma_bf16(sc[2*nf2+1], ah, bh[2], bh[3]);
                        mma_bf16(sc[2*nf2],   ah, bl[0], bl[1]);
                        mma_bf16(sc[2*nf2+1], ah, bl[2], bl[3]);
                        mma_bf16(sc[2*nf2],   av, bh[0], bh[1]);
                        mma_bf16(sc[2*nf2+1], av, bh[2], bh[3]);
                    }
                }

                const int r_lo = rmin + (lane >> 2);
                if (n0 + 63 > rmin) {
#pragma unroll
                    for (int nf = 0; nf < 8; ++nf) {
                        int cbase = n0 + nf * 8 + ((lane & 3) << 1);
#pragma unroll
                        for (int e = 0; e < 4; ++e) {
                            int col = cbase + (e & 1);
                            int row = r_lo + ((e >> 1) << 3);
                            if (col > row) sc[nf][e] = -CUDART_INF_F;
                        }
                    }
                }

                float mx0 = -CUDART_INF_F, mx1 = -CUDART_INF_F;
#pragma unroll
                for (int nf = 0; nf < 8; ++nf) {
                    mx0 = fmaxf(mx0, fmaxf(sc[nf][0], sc[nf][1]));
                    mx1 = fmaxf(mx1, fmaxf(sc[nf][2], sc[nf][3]));
                }
                mx0 = fmaxf(mx0, __shfl_xor_sync(0xffffffffu, mx0, 1));
                mx0 = fmaxf(mx0, __shfl_xor_sync(0xffffffffu, mx0, 2));
                mx1 = fmaxf(mx1, __shfl_xor_sync(0xffffffffu, mx1, 1));
                mx1 = fmaxf(mx1, __shfl_xor_sync(0xffffffffu, mx1, 2));
                float mn0 = fmaxf(m0, mx0), mn1 = fmaxf(m1, mx1);
                float al0 = __expf(m0 - mn0), al1 = __expf(m1 - mn1);
                float rs0 = 0.f, rs1 = 0.f;
#pragma unroll
                for (int nf = 0; nf < 8; ++nf) {
                    sc[nf][0] = __expf(sc[nf][0] - mn0);
                    sc[nf][1] = __expf(sc[nf][1] - mn0);
                    sc[nf][2] = __expf(sc[nf][2] - mn1);
                    sc[nf][3] = __expf(sc[nf][3] - mn1);
                    rs0 += sc[nf][0] + sc[nf][1];
                    rs1 += sc[nf][2] + sc[nf][3];
                }
                rs0 += __shfl_xor_sync(0xffffffffu, rs0, 1);
                rs0 += __shfl_xor_sync(0xffffffffu, rs0, 2);
                rs1 += __shfl_xor_sync(0xffffffffu, rs1, 1);
                rs1 += __shfl_xor_sync(0xffffffffu, rs1, 2);
                l0 = l0 * al0 + rs0;  l1 = l1 * al1 + rs1;
                m0 = mn0;             m1 = mn1;
#pragma unroll
                for (int nf = 0; nf < 16; ++nf) {
                    o[nf][0] *= al0; o[nf][1] *= al0;
                    o[nf][2] *= al1; o[nf][3] *= al1;
                }

                const uint32_t vh_b = sb + OVH + buf * (128 * VPB) + b_row * VPB + b_koff;
                const uint32_t vl_b = sb + OVL + buf * (128 * VPB) + b_row * VPB + b_koff;
#pragma unroll
                for (int t = 0; t < 4; ++t) {
                    uint32_t pah[4], pal[4];
                    hilo2(sc[2*t][0],   sc[2*t][1],   pah[0], pal[0]);
                    hilo2(sc[2*t][2],   sc[2*t][3],   pah[1], pal[1]);
                    hilo2(sc[2*t+1][0], sc[2*t+1][1], pah[2], pal[2]);
                    hilo2(sc[2*t+1][2], sc[2*t+1][3], pah[3], pal[3]);
#pragma unroll
                    for (int nd2 = 0; nd2 < 8; ++nd2) {
                        uint32_t vh[4], vl[4];
                        ldsm4(vh, vh_b + nd2 * (16 * VPB) + t * 32);
                        ldsm4(vl, vl_b + nd2 * (16 * VPB) + t * 32);
                        mma_bf16(o[2*nd2],   pah, vh[0], vh[1]);
                        mma_bf16(o[2*nd2+1], pah, vh[2], vh[3]);
                        mma_bf16(o[2*nd2],   pah, vl[0], vl[1]);
                        mma_bf16(o[2*nd2+1], pah, vl[2], vl[3]);
                        mma_bf16(o[2*nd2],   pal, vh[0], vh[1]);
                        mma_bf16(o[2*nd2+1], pal, vh[2], vh[3]);
                    }
                }
            }
            __syncthreads();
        }

        const float il0 = 1.f / l0, il1 = 1.f / l1;
        const int srow = rmin + (lane >> 2);
        const int dq   = (lane & 3) << 1;
#pragma unroll
        for (int nf = 0; nf < 16; ++nf) {
            int d = nf * 8 + dq;
            size_t base = (size_t)(b * NS) * ND + (size_t)h * DH + d;
            uint32_t hp, lp;
            hilo2(o[nf][0] * il0, o[nf][1] * il0, hp, lp);
            *reinterpret_cast<uint32_t*>(Oh + base + (size_t)srow * ND) = hp;
            *reinterpret_cast<uint32_t*>(Ol + base + (size_t)srow * ND) = lp;
            hilo2(o[nf][2] * il1, o[nf][3] * il1, hp, lp);
            *reinterpret_cast<uint32_t*>(Oh + base + (size_t)(srow + 8) * ND) = hp;
            *reinterpret_cast<uint32_t*>(Ol + base + (size_t)(srow + 8) * ND) = lp;
        }
    }
}

// ---------------------------------------------------------------------------
extern "C" void kernel_launch(void* const* d_in, const int* in_sizes, int n_in,
                              void* d_out, int out_size) {
    const float* x  = (const float*)d_in[0];
    const float* Wq = (const float*)d_in[1];
    const float* Wk = (const float*)d_in[2];
    const float* Wv = (const float*)d_in[3];
    const float* Wo = (const float*)d_in[4];

    __nv_bfloat16 *xh, *xl, *wh, *wl, *qh, *ql, *kh, *kl, *vth, *vtl;
    float2* rp;
    cudaGetSymbolAddress((void**)&xh,  g_xh);
    cudaGetSymbolAddress((void**)&xl,  g_xl);
    cudaGetSymbolAddress((void**)&wh,  g_wh);
    cudaGetSymbolAddress((void**)&wl,  g_wl);
    cudaGetSymbolAddress((void**)&qh,  g_qh);
    cudaGetSymbolAddress((void**)&ql,  g_ql);
    cudaGetSymbolAddress((void**)&kh,  g_kh);
    cudaGetSymbolAddress((void**)&kl,  g_kl);
    cudaGetSymbolAddress((void**)&vth, g_vth);
    cudaGetSymbolAddress((void**)&vtl, g_vtl);
    cudaGetSymbolAddress((void**)&rp,  g_rope);

    cudaFuncSetAttribute(gemm_qkv, cudaFuncAttributeMaxDynamicSharedMemorySize, GSMEM);
    cudaFuncSetAttribute(gemm_out, cudaFuncAttributeMaxDynamicSharedMemorySize, GSMEM);
    cudaFuncSetAttribute(flash_mma, cudaFuncAttributeMaxDynamicSharedMemorySize, FSMEM);

    OutPtrs op{qh, ql, kh, kl, vth, vtl};

    const int actblocks = NM * ND / (256 * 4);

    // Independent prep: rope table + activation split + weight transpose-splits.
    rope_table<<<NS * 64 / 256, 256>>>(rp);
    split_act<<<actblocks, 256>>>(x, xh, xl);
    split_wT4<<<dim3(ND / 32, ND / 32, 4), dim3(32, 8)>>>(Wq, Wk, Wv, Wo, wh, wl);

    // Merged Q/K/V projections (one launch, 1536 CTAs, 512 threads each).
    gemm_qkv<<<dim3(48, NM / 128), 512, GSMEM>>>(xh, xl, wh, wl, rp, op);

    // Flash attention: paired q-tiles, 256 CTAs; writes bf16 hi/lo into xh/xl.
    flash_mma<<<dim3(NQT / 2, NH, NB), 256, FSMEM>>>(qh, ql, kh, kl, vth, vtl, xh, xl);

    // Final projection (weight index 3).
    gemm_out<<<dim3(ND / 128, NM / 128), 512, GSMEM>>>(
        xh, xl, wh + (size_t)3 * ND * ND, wl + (size_t)3 * ND * ND, (float*)d_out);
}

// round 17
// speedup vs baseline: 1.1201x; 1.1201x over previous
#include <cuda_runtime.h>
#include <cuda_bf16.h>
#include <math.h>
#include <math_constants.h>
#include <cstdint>

// Problem constants
#define NB 2
#define NS 2048
#define ND 2048
#define NH 16
#define DH 128
#define NM 4096   // NB*NS

#define L2_10K_OVER_64 0.2076205059304602f   // log2(10000)/64
#define QSCALE 0.08838834764831845f          // 1/sqrt(128)

// Scratch: sanctioned __device__ globals (no runtime allocation).
__device__ __nv_bfloat16 g_xh [NM*ND];         // activation hi (x, then attn-out)
__device__ __nv_bfloat16 g_xl [NM*ND];         // activation lo
__device__ __nv_bfloat16 g_wh [4*ND*ND];       // transposed weights hi [w][n][k]
__device__ __nv_bfloat16 g_wl [4*ND*ND];       // transposed weights lo
__device__ __nv_bfloat16 g_qh [NB*NH*NS*DH];   // Q hi  (B,H,S,D), roped+scaled
__device__ __nv_bfloat16 g_ql [NB*NH*NS*DH];
__device__ __nv_bfloat16 g_kh [NB*NH*NS*DH];   // K hi  (B,H,S,D), roped
__device__ __nv_bfloat16 g_kl [NB*NH*NS*DH];
__device__ __nv_bfloat16 g_vth[NB*NH*DH*NS];   // V^T hi (B,H,D,S)
__device__ __nv_bfloat16 g_vtl[NB*NH*DH*NS];
__device__ float2 g_rope[NS*64];               // (cos,sin) per (s, freq-index)

struct OutPtrs {
    __nv_bfloat16 *qh, *ql, *kh, *kl, *vth, *vtl;
};

// ============================ PTX helpers ==================================
__device__ __forceinline__ uint32_t smem_u32(const void* p) {
    uint32_t a;
    asm("{ .reg .u64 t; cvta.to.shared.u64 t, %1; cvt.u32.u64 %0, t; }"
        : "=r"(a) : "l"(p));
    return a;
}

__device__ __forceinline__ void ldsm4(uint32_t* r, uint32_t addr) {
    asm volatile("ldmatrix.sync.aligned.m8n8.x4.shared.b16 {%0,%1,%2,%3}, [%4];"
        : "=r"(r[0]), "=r"(r[1]), "=r"(r[2]), "=r"(r[3]) : "r"(addr));
}

__device__ __forceinline__ void mma_bf16(float* c, const uint32_t* a,
                                         uint32_t b0, uint32_t b1) {
    asm volatile(
        "mma.sync.aligned.m16n8k16.row.col.f32.bf16.bf16.f32 "
        "{%0,%1,%2,%3}, {%4,%5,%6,%7}, {%8,%9}, {%0,%1,%2,%3};"
        : "+f"(c[0]), "+f"(c[1]), "+f"(c[2]), "+f"(c[3])
        : "r"(a[0]), "r"(a[1]), "r"(a[2]), "r"(a[3]), "r"(b0), "r"(b1));
}

__device__ __forceinline__ void cpa16(uint32_t saddr, const void* gaddr) {
    asm volatile("cp.async.cg.shared.global [%0], [%1], 16;"
                 :: "r"(saddr), "l"(gaddr));
}
#define CPA_COMMIT() asm volatile("cp.async.commit_group;")
#define CPA_WAIT0()  asm volatile("cp.async.wait_group 0;")

// pack (a,b) into bf16x2 hi word + bf16x2 lo-residual word
__device__ __forceinline__ void hilo2(float a, float b, uint32_t& hi, uint32_t& lo) {
    __nv_bfloat16 ha = __float2bfloat16_rn(a);
    __nv_bfloat16 hb = __float2bfloat16_rn(b);
    __nv_bfloat162 hp(ha, hb);
    __nv_bfloat162 lp = __floats2bfloat162_rn(a - __bfloat162float(ha),
                                              b - __bfloat162float(hb));
    hi = *reinterpret_cast<uint32_t*>(&hp);
    lo = *reinterpret_cast<uint32_t*>(&lp);
}

// =========================== prep kernels ==================================
__global__ void __launch_bounds__(256) split_act(const float* __restrict__ in,
                                                 __nv_bfloat16* __restrict__ hi,
                                                 __nv_bfloat16* __restrict__ lo) {
    int i = (blockIdx.x * 256 + threadIdx.x) * 4;
    float4 v = *(const float4*)(in + i);
    uint32_t h0, l0, h1, l1;
    hilo2(v.x, v.y, h0, l0);
    hilo2(v.z, v.w, h1, l1);
    *(uint2*)(hi + i) = make_uint2(h0, h1);
    *(uint2*)(lo + i) = make_uint2(l0, l1);
}

// RoPE table: exactly the same FP formula the epilogue used inline.
__global__ void __launch_bounds__(256) rope_table(float2* __restrict__ tab) {
    int idx = blockIdx.x * 256 + threadIdx.x;     // 0 .. NS*64-1
    int ss  = idx >> 6;
    int i   = idx & 63;
    float inv = exp2f(-(float)i * L2_10K_OVER_64);
    float s, c;
    sincosf((float)ss * inv, &s, &c);
    tab[idx] = make_float2(c, s);
}

// All four W[k][n] fp32 -> Wt hi/lo bf16 [w][n][k] in ONE launch (grid.z = w)
__global__ void __launch_bounds__(256) split_wT4(
    const float* __restrict__ W0, const float* __restrict__ W1,
    const float* __restrict__ W2, const float* __restrict__ W3,
    __nv_bfloat16* __restrict__ th, __nv_bfloat16* __restrict__ tl) {
    __shared__ float t[32][33];
    const int w  = blockIdx.z;
    const float* W = (w == 0) ? W0 : (w == 1) ? W1 : (w == 2) ? W2 : W3;
    const size_t wo = (size_t)w * ND * ND;
    const int bx = blockIdx.x * 32;   // n tile
    const int by = blockIdx.y * 32;   // k tile
    const int tx = threadIdx.x, ty = threadIdx.y;
#pragma unroll
    for (int j = ty; j < 32; j += 8)
        t[j][tx] = W[(size_t)(by + j) * ND + bx + tx];
    __syncthreads();
#pragma unroll
    for (int j = ty; j < 32; j += 8) {
        float v = t[tx][j];           // = W[by+tx][bx+j]
        __nv_bfloat16 h = __float2bfloat16_rn(v);
        __nv_bfloat16 l = __float2bfloat16_rn(v - __bfloat162float(h));
        th[wo + (size_t)(bx + j) * ND + by + tx] = h;
        tl[wo + (size_t)(bx + j) * ND + by + tx] = l;
    }
}

// ===================== HMMA bf16x3 GEMM mainloop ===========================
// 256 threads, 8 warps (wm 4 x wn 2), warp tile 32x64, CTA 128x128,
// K_blk = 32, cp.async double buffer, occ 2. ONE barrier per k-iteration:
// next-stage cp.async is issued AFTER the head sync, so every reader of the
// target buffer has already passed a sync -> trailing barrier is redundant.
#define APITCH 80
#define TILE_BYTES (128 * APITCH)
#define STAGE_BYTES (4 * TILE_BYTES)
#define GSMEM (2 * STAGE_BYTES)            // 81920

// Arow/Brow pre-offset to the CTA tile's first row; row stride ND.
__device__ __forceinline__ void mma_mainloop(
    float acc[2][8][4],
    const __nv_bfloat16* __restrict__ ArowH, const __nv_bfloat16* __restrict__ ArowL,
    const __nv_bfloat16* __restrict__ BrowH, const __nv_bfloat16* __restrict__ BrowL,
    uint32_t sbase, int tid, int wm, int wn, int lane)
{
    auto load_stage = [&](int buf, int k0) {
#pragma unroll
        for (int t = 0; t < 8; ++t) {
            int id   = tid + t * 256;
            int tile = id >> 9;
            int rem  = id & 511;
            int r    = rem >> 2;
            int c    = rem & 3;
            uint32_t so = sbase + buf * STAGE_BYTES + tile * TILE_BYTES
                        + r * APITCH + c * 16;
            const __nv_bfloat16* g;
            if      (tile == 0) g = ArowH + (size_t)r * ND + k0 + c * 8;
            else if (tile == 1) g = ArowL + (size_t)r * ND + k0 + c * 8;
            else if (tile == 2) g = BrowH + (size_t)r * ND + k0 + c * 8;
            else                g = BrowL + (size_t)r * ND + k0 + c * 8;
            cpa16(so, g);
        }
        CPA_COMMIT();
    };

    load_stage(0, 0);

    for (int it = 0; it < 64; ++it) {
        const int buf = it & 1;
        CPA_WAIT0();           // buf data arrived (and prior groups drained)
        __syncthreads();       // all warps done reading buf^1 (last iter)
        if (it + 1 < 64) load_stage(buf ^ 1, (it + 1) * 32);

        const uint32_t sA  = sbase + buf * STAGE_BYTES;
        const uint32_t sAl = sA + TILE_BYTES;
        const uint32_t sB  = sA + 2 * TILE_BYTES;
        const uint32_t sBl = sA + 3 * TILE_BYTES;

#pragma unroll
        for (int ks = 0; ks < 2; ++ks) {
            const int akb = ks * 32 + (lane >> 4) * 16;
            uint32_t ah[2][4], al[2][4];
#pragma unroll
            for (int mf = 0; mf < 2; ++mf) {
                uint32_t ro = (wm * 32 + mf * 16 + (lane & 15)) * APITCH + akb;
                ldsm4(ah[mf], sA  + ro);
                ldsm4(al[mf], sAl + ro);
            }
            const int brow = wn * 64 + (lane & 7) + ((lane >> 4) << 3);
            const int bkb  = ks * 32 + ((lane >> 3) & 1) * 16;
#pragma unroll
            for (int nf2 = 0; nf2 < 4; ++nf2) {
                uint32_t bo = (brow + nf2 * 16) * APITCH + bkb;
                uint32_t bh[4], bl[4];
                ldsm4(bh, sB  + bo);
                ldsm4(bl, sBl + bo);
                // Per-acc order unchanged (hh -> hl -> lh) => bitwise-identical.
#pragma unroll
                for (int half = 0; half < 2; ++half)
#pragma unroll
                    for (int mf = 0; mf < 2; ++mf)
                        mma_bf16(acc[mf][nf2 * 2 + half], ah[mf],
                                 bh[half * 2], bh[half * 2 + 1]);
#pragma unroll
                for (int half = 0; half < 2; ++half)
#pragma unroll
                    for (int mf = 0; mf < 2; ++mf)
                        mma_bf16(acc[mf][nf2 * 2 + half], ah[mf],
                                 bl[half * 2], bl[half * 2 + 1]);
#pragma unroll
                for (int half = 0; half < 2; ++half)
#pragma unroll
                    for (int mf = 0; mf < 2; ++mf)
                        mma_bf16(acc[mf][nf2 * 2 + half], al[mf],
                                 bh[half * 2], bh[half * 2 + 1]);
            }
        }
    }
}

// ---- merged Q/K/V projections: grid.x = 48 (mode = blockIdx.x >> 4) ----
__global__ void __launch_bounds__(256, 2) gemm_qkv(
    const __nv_bfloat16* __restrict__ Ah, const __nv_bfloat16* __restrict__ Al,
    const __nv_bfloat16* __restrict__ Wh, const __nv_bfloat16* __restrict__ Wl,
    const float2* __restrict__ rope, OutPtrs op)
{
    extern __shared__ char smc[];
    const uint32_t sbase = smem_u32(smc);
    const int tid  = threadIdx.x;
    const int wid  = tid >> 5;
    const int lane = tid & 31;
    const int wm   = wid & 3;
    const int wn   = wid >> 2;
    const int mode = blockIdx.x >> 4;              // 0=Q 1=K 2=V
    const int col0 = (blockIdx.x & 15) * 128;
    const int row0 = blockIdx.y * 128;
    const size_t wo = (size_t)mode * ND * ND;

    float acc[2][8][4];
#pragma unroll
    for (int mf = 0; mf < 2; ++mf)
#pragma unroll
        for (int nf = 0; nf < 8; ++nf)
#pragma unroll
            for (int e = 0; e < 4; ++e) acc[mf][nf][e] = 0.f;

    mma_mainloop(acc, Ah + (size_t)row0 * ND, Al + (size_t)row0 * ND,
                 Wh + wo + (size_t)col0 * ND, Wl + wo + (size_t)col0 * ND,
                 sbase, tid, wm, wn, lane);

    __nv_bfloat16* Ch = (mode == 0) ? op.qh : (mode == 1) ? op.kh : op.vth;
    __nv_bfloat16* Cl = (mode == 0) ? op.ql : (mode == 1) ? op.kl : op.vtl;

#pragma unroll
    for (int mf = 0; mf < 2; ++mf) {
        const int mrow = row0 + wm * 32 + mf * 16 + (lane >> 2);
#pragma unroll
        for (int rr = 0; rr < 2; ++rr) {
            const int m  = mrow + rr * 8;
            const int bb = m >> 11, ss = m & 2047;
#pragma unroll
            for (int nf = 0; nf < 8; ++nf) {
                const int cloc = wn * 64 + nf * 8 + ((lane & 3) << 1);
                const int col  = col0 + cloc;
                const int h    = col >> 7;
                const int d    = cloc & 127;
                float v0 = acc[mf][nf][rr * 2 + 0];
                float v1 = acc[mf][nf][rr * 2 + 1];
                if (mode == 2) {
                    size_t vb = ((size_t)(bb * NH + h) * DH + d) * NS + ss;
                    __nv_bfloat16 h0 = __float2bfloat16_rn(v0);
                    __nv_bfloat16 h1 = __float2bfloat16_rn(v1);
                    Ch[vb]      = h0;
                    Ch[vb + NS] = h1;
                    Cl[vb]      = __float2bfloat16_rn(v0 - __bfloat162float(h0));
                    Cl[vb + NS] = __float2bfloat16_rn(v1 - __bfloat162float(h1));
                } else {
                    size_t ob = (((size_t)(bb * NH + h) * NS + ss) << 7) + d;
                    // d even, so (d&63) even: one aligned float4 covers both
                    // (cos_e, sin_e, cos_o, sin_o) — same values sincosf gave.
                    float4 cs = *(const float4*)(rope + (size_t)ss * 64 + (d & 63));
                    float o0 = v0 * cs.x - v1 * cs.y;
                    float o1 = v1 * cs.z + v0 * cs.w;
                    if (mode == 0) { o0 *= QSCALE; o1 *= QSCALE; }
                    uint32_t hp, lp;
                    hilo2(o0, o1, hp, lp);
                    *reinterpret_cast<uint32_t*>(Ch + ob) = hp;
                    *reinterpret_cast<uint32_t*>(Cl + ob) = lp;
                }
            }
        }
    }
}

// ---- final projection: fp32 row-major out ----
__global__ void __launch_bounds__(256, 2) gemm_out(
    const __nv_bfloat16* __restrict__ Ah, const __nv_bfloat16* __restrict__ Al,
    const __nv_bfloat16* __restrict__ Wh, const __nv_bfloat16* __restrict__ Wl,
    float* __restrict__ C)
{
    extern __shared__ char smc[];
    const uint32_t sbase = smem_u32(smc);
    const int tid  = threadIdx.x;
    const int wid  = tid >> 5;
    const int lane = tid & 31;
    const int wm   = wid & 3;
    const int wn   = wid >> 2;
    const int col0 = blockIdx.x * 128;
    const int row0 = blockIdx.y * 128;

    float acc[2][8][4];
#pragma unroll
    for (int mf = 0; mf < 2; ++mf)
#pragma unroll
        for (int nf = 0; nf < 8; ++nf)
#pragma unroll
            for (int e = 0; e < 4; ++e) acc[mf][nf][e] = 0.f;

    mma_mainloop(acc, Ah + (size_t)row0 * ND, Al + (size_t)row0 * ND,
                 Wh + (size_t)col0 * ND, Wl + (size_t)col0 * ND,
                 sbase, tid, wm, wn, lane);

#pragma unroll
    for (int mf = 0; mf < 2; ++mf) {
        const int mrow = row0 + wm * 32 + mf * 16 + (lane >> 2);
#pragma unroll
        for (int rr = 0; rr < 2; ++rr) {
            const int m = mrow + rr * 8;
#pragma unroll
            for (int nf = 0; nf < 8; ++nf) {
                const int col = col0 + wn * 64 + nf * 8 + ((lane & 3) << 1);
                *(float2*)(C + (size_t)m * ND + col) =
                    make_float2(acc[mf][nf][rr * 2 + 0], acc[mf][nf][rr * 2 + 1]);
            }
        }
    }
}

// ======================= flash attention (mma.sync) ========================
// Paired q-tiles per CTA, grid 256 CTAs. ONE barrier per k-iteration (same
// argument as the GEMM); one extra sync per rep protects the Q-tile reload.
#define NQT (NS / 128)                // 16
#define QPB 272
#define VPB 144
#define OQH 0
#define OQL (OQH + 128*QPB)
#define OKH (OQL + 128*QPB)
#define OKL (OKH + 2*64*QPB)
#define OVH (OKL + 2*64*QPB)
#define OVL (OVH + 2*128*VPB)
#define FSMEM (OVL + 2*128*VPB)       // 212992

__global__ void __launch_bounds__(256, 1) flash_mma(
    const __nv_bfloat16* __restrict__ Qh, const __nv_bfloat16* __restrict__ Ql,
    const __nv_bfloat16* __restrict__ Kh, const __nv_bfloat16* __restrict__ Kl,
    const __nv_bfloat16* __restrict__ Vth, const __nv_bfloat16* __restrict__ Vtl,
    __nv_bfloat16* __restrict__ Oh, __nv_bfloat16* __restrict__ Ol)
{
    extern __shared__ char smc[];
    const uint32_t sb = smem_u32(smc);
    const int tid = threadIdx.x, wid = tid >> 5, lane = tid & 31;
    const int h  = blockIdx.y, b = blockIdx.z;
    const size_t ho = (size_t)(b * NH + h) * NS * DH;

    const uint32_t a_off  = (uint32_t)((wid * 16 + (lane & 15)) * QPB + (lane >> 4) * 16);
    const uint32_t b_row  = (uint32_t)((lane & 7) + ((lane >> 4) << 3));
    const uint32_t b_koff = (uint32_t)(((lane >> 3) & 1) * 16);

    auto loadKV = [&](int buf, int n0) {
#pragma unroll
        for (int t = 0; t < 8; ++t) {
            int id  = tid + t * 256;
            int arr = id >> 10;
            int rem = id & 1023;
            int r = rem >> 4, c = rem & 15;
            uint32_t so = sb + (arr ? OKL : OKH) + buf * (64 * QPB) + r * QPB + c * 16;
            const __nv_bfloat16* g = (arr ? Kl : Kh) + ho + (size_t)(n0 + r) * DH + c * 8;
            cpa16(so, g);
        }
#pragma unroll
        for (int t = 0; t < 8; ++t) {
            int id  = tid + t * 256;
            int arr = id >> 10;
            int rem = id & 1023;
            int r = rem >> 3, c = rem & 7;
            uint32_t so = sb + (arr ? OVL : OVH) + buf * (128 * VPB) + r * VPB + c * 16;
            const __nv_bfloat16* g = (arr ? Vtl : Vth) + ho + (size_t)r * NS + n0 + c * 8;
            cpa16(so, g);
        }
        CPA_COMMIT();
    };

#pragma unroll 1
    for (int rep = 0; rep < 2; ++rep) {
        const int qt = rep == 0 ? (NQT - 1 - (int)blockIdx.x) : (int)blockIdx.x;
        const int q0 = qt * 128;

        // Q tile for this rep (rep 1 load is protected by the end-of-rep sync)
#pragma unroll
        for (int t = 0; t < 16; ++t) {
            int id  = tid + t * 256;
            int arr = id >> 11;
            int rem = id & 2047;
            int r = rem >> 4, c = rem & 15;
            uint32_t so = sb + (arr ? OQL : OQH) + r * QPB + c * 16;
            const __nv_bfloat16* g = (arr ? Ql : Qh) + ho + (size_t)(q0 + r) * DH + c * 8;
            cpa16(so, g);
        }
        loadKV(0, 0);      // commits Q + KV0 as one group

        const int rmin = q0 + wid * 16;
        float o[16][4];
#pragma unroll
        for (int nf = 0; nf < 16; ++nf)
#pragma unroll
            for (int e = 0; e < 4; ++e) o[nf][e] = 0.f;
        float m0 = -CUDART_INF_F, m1 = -CUDART_INF_F, l0 = 0.f, l1 = 0.f;

        const int niter = q0 / 64 + 2;
        for (int it = 0; it < niter; ++it) {
            const int n0 = it * 64, buf = it & 1;
            CPA_WAIT0();       // buf (and Q on it=0) arrived
            __syncthreads();   // all warps done reading buf^1
            if (it + 1 < niter) loadKV(buf ^ 1, (it + 1) * 64);

            if (n0 <= rmin + 15) {
                float sc[8][4];
#pragma unroll
                for (int nf = 0; nf < 8; ++nf)
#pragma unroll
                    for (int e = 0; e < 4; ++e) sc[nf][e] = 0.f;

                const uint32_t kh_b = sb + OKH + buf * (64 * QPB) + b_row * QPB + b_koff;
                const uint32_t kl_b = sb + OKL + buf * (64 * QPB) + b_row * QPB + b_koff;
#pragma unroll 4
                for (int t = 0; t < 8; ++t) {
                    uint32_t ah[4], av[4];
                    ldsm4(ah, sb + OQH + a_off + t * 32);
                    ldsm4(av, sb + OQL + a_off + t * 32);
#pragma unroll
                    for (int nf2 = 0; nf2 < 4; ++nf2) {
                        uint32_t bh[4], bl[4];
                        ldsm4(bh, kh_b + nf2 * (16 * QPB) + t * 32);
                        ldsm4(bl, kl_b + nf2 * (16 * QPB) + t * 32);
                        mma_bf16(sc[2*nf2],   ah, bh[0], bh[1]);
                        mma_bf16(sc[2*nf2+1], ah, bh[2], bh[3]);
                        mma_bf16(sc[2*nf2],   ah, bl[0], bl[1]);
                        mma_bf16(sc[2*nf2+1], ah, bl[2], bl[3]);
                        mma_bf16(sc[2*nf2],   av, bh[0], bh[1]);
                        mma_bf16(sc[2*nf2+1], av, bh[2], bh[3]);
                    }
                }

                const int r_lo = rmin + (lane >> 2);
                if (n0 + 63 > rmin) {
#pragma unroll
                    for (int nf = 0; nf < 8; ++nf) {
                        int cbase = n0 + nf * 8 + ((lane & 3) << 1);
#pragma unroll
                        for (int e = 0; e < 4; ++e) {
                            int col = cbase + (e & 1);
                            int row = r_lo + ((e >> 1) << 3);
                            if (col > row) sc[nf][e] = -CUDART_INF_F;
                        }
                    }
                }

                float mx0 = -CUDART_INF_F, mx1 = -CUDART_INF_F;
#pragma unroll
                for (int nf = 0; nf < 8; ++nf) {
                    mx0 = fmaxf(mx0, fmaxf(sc[nf][0], sc[nf][1]));
                    mx1 = fmaxf(mx1, fmaxf(sc[nf][2], sc[nf][3]));
                }
                mx0 = fmaxf(mx0, __shfl_xor_sync(0xffffffffu, mx0, 1));
                mx0 = fmaxf(mx0, __shfl_xor_sync(0xffffffffu, mx0, 2));
                mx1 = fmaxf(mx1, __shfl_xor_sync(0xffffffffu, mx1, 1));
                mx1 = fmaxf(mx1, __shfl_xor_sync(0xffffffffu, mx1, 2));
                float mn0 = fmaxf(m0, mx0), mn1 = fmaxf(m1, mx1);
                float al0 = __expf(m0 - mn0), al1 = __expf(m1 - mn1);
                float rs0 = 0.f, rs1 = 0.f;
#pragma unroll
                for (int nf = 0; nf < 8; ++nf) {
                    sc[nf][0] = __expf(sc[nf][0] - mn0);
                    sc[nf][1] = __expf(sc[nf][1] - mn0);
                    sc[nf][2] = __expf(sc[nf][2] - mn1);
                    sc[nf][3] = __expf(sc[nf][3] - mn1);
                    rs0 += sc[nf][0] + sc[nf][1];
                    rs1 += sc[nf][2] + sc[nf][3];
                }
                rs0 += __shfl_xor_sync(0xffffffffu, rs0, 1);
                rs0 += __shfl_xor_sync(0xffffffffu, rs0, 2);
                rs1 += __shfl_xor_sync(0xffffffffu, rs1, 1);
                rs1 += __shfl_xor_sync(0xffffffffu, rs1, 2);
                l0 = l0 * al0 + rs0;  l1 = l1 * al1 + rs1;
                m0 = mn0;             m1 = mn1;
#pragma unroll
                for (int nf = 0; nf < 16; ++nf) {
                    o[nf][0] *= al0; o[nf][1] *= al0;
                    o[nf][2] *= al1; o[nf][3] *= al1;
                }

                const uint32_t vh_b = sb + OVH + buf * (128 * VPB) + b_row * VPB + b_koff;
                const uint32_t vl_b = sb + OVL + buf * (128 * VPB) + b_row * VPB + b_koff;
#pragma unroll
                for (int t = 0; t < 4; ++t) {
                    uint32_t pah[4], pal[4];
                    hilo2(sc[2*t][0],   sc[2*t][1],   pah[0], pal[0]);
                    hilo2(sc[2*t][2],   sc[2*t][3],   pah[1], pal[1]);
                    hilo2(sc[2*t+1][0], sc[2*t+1][1], pah[2], pal[2]);
                    hilo2(sc[2*t+1][2], sc[2*t+1][3], pah[3], pal[3]);
#pragma unroll
                    for (int nd2 = 0; nd2 < 8; ++nd2) {
                        uint32_t vh[4], vl[4];
                        ldsm4(vh, vh_b + nd2 * (16 * VPB) + t * 32);
                        ldsm4(vl, vl_b + nd2 * (16 * VPB) + t * 32);
                        mma_bf16(o[2*nd2],   pah, vh[0], vh[1]);
                        mma_bf16(o[2*nd2+1], pah, vh[2], vh[3]);
                        mma_bf16(o[2*nd2],   pah, vl[0], vl[1]);
                        mma_bf16(o[2*nd2+1], pah, vl[2], vl[3]);
                        mma_bf16(o[2*nd2],   pal, vh[0], vh[1]);
                        mma_bf16(o[2*nd2+1], pal, vh[2], vh[3]);
                    }
                }
            }
        }
        __syncthreads();   // all warps done with Q/K/V smem before next rep

        const float il0 = 1.f / l0, il1 = 1.f / l1;
        const int srow = rmin + (lane >> 2);
        const int dq   = (lane & 3) << 1;
#pragma unroll
        for (int nf = 0; nf < 16; ++nf) {
            int d = nf * 8 + dq;
            size_t base = (size_t)(b * NS) * ND + (size_t)h * DH + d;
            uint32_t hp, lp;
            hilo2(o[nf][0] * il0, o[nf][1] * il0, hp, lp);
            *reinterpret_cast<uint32_t*>(Oh + base + (size_t)srow * ND) = hp;
            *reinterpret_cast<uint32_t*>(Ol + base + (size_t)srow * ND) = lp;
            hilo2(o[nf][2] * il1, o[nf][3] * il1, hp, lp);
            *reinterpret_cast<uint32_t*>(Oh + base + (size_t)(srow + 8) * ND) = hp;
            *reinterpret_cast<uint32_t*>(Ol + base + (size_t)(srow + 8) * ND) = lp;
        }
    }
}

// ---------------------------------------------------------------------------
extern "C" void kernel_launch(void* const* d_in, const int* in_sizes, int n_in,
                              void* d_out, int out_size) {
    const float* x  = (const float*)d_in[0];
    const float* Wq = (const float*)d_in[1];
    const float* Wk = (const float*)d_in[2];
    const float* Wv = (const float*)d_in[3];
    const float* Wo = (const float*)d_in[4];

    __nv_bfloat16 *xh, *xl, *wh, *wl, *qh, *ql, *kh, *kl, *vth, *vtl;
    float2* rp;
    cudaGetSymbolAddress((void**)&xh,  g_xh);
    cudaGetSymbolAddress((void**)&xl,  g_xl);
    cudaGetSymbolAddress((void**)&wh,  g_wh);
    cudaGetSymbolAddress((void**)&wl,  g_wl);
    cudaGetSymbolAddress((void**)&qh,  g_qh);
    cudaGetSymbolAddress((void**)&ql,  g_ql);
    cudaGetSymbolAddress((void**)&kh,  g_kh);
    cudaGetSymbolAddress((void**)&kl,  g_kl);
    cudaGetSymbolAddress((void**)&vth, g_vth);
    cudaGetSymbolAddress((void**)&vtl, g_vtl);
    cudaGetSymbolAddress((void**)&rp,  g_rope);

    cudaFuncSetAttribute(gemm_qkv, cudaFuncAttributeMaxDynamicSharedMemorySize, GSMEM);
    cudaFuncSetAttribute(gemm_out, cudaFuncAttributeMaxDynamicSharedMemorySize, GSMEM);
    cudaFuncSetAttribute(flash_mma, cudaFuncAttributeMaxDynamicSharedMemorySize, FSMEM);

    OutPtrs op{qh, ql, kh, kl, vth, vtl};

    const int actblocks = NM * ND / (256 * 4);

    // Independent prep: rope table + activation split + weight transpose-splits.
    rope_table<<<NS * 64 / 256, 256>>>(rp);
    split_act<<<actblocks, 256>>>(x, xh, xl);
    split_wT4<<<dim3(ND / 32, ND / 32, 4), dim3(32, 8)>>>(Wq, Wk, Wv, Wo, wh, wl);

    // Merged Q/K/V projections (one launch, 1536 CTAs, 256 threads each).
    gemm_qkv<<<dim3(48, NM / 128), 256, GSMEM>>>(xh, xl, wh, wl, rp, op);

    // Flash attention: paired q-tiles, 256 CTAs; writes bf16 hi/lo into xh/xl.
    flash_mma<<<dim3(NQT / 2, NH, NB), 256, FSMEM>>>(qh, ql, kh, kl, vth, vtl, xh, xl);

    // Final projection (weight index 3).
    gemm_out<<<dim3(ND / 128, NM / 128), 256, GSMEM>>>(
        xh, xl, wh + (size_t)3 * ND * ND, wl + (size_t)3 * ND * ND, (float*)d_out);
}